// round 13
// baseline (speedup 1.0000x reference)
#include <cuda_runtime.h>

namespace {
constexpr int T_  = 1024;
constexpr int S_  = 64;
constexpr int D_  = 256;
constexpr int TP_ = 8;
constexpr int C_  = 65;   // 2*H*N_K + 1
}

__device__ __forceinline__ unsigned pack_sgnabs(int v) {
    unsigned a = (unsigned)(v < 0 ? -v : v);
    return a | (v < 0 ? 0x80000000u : 0u);
}

__global__ __launch_bounds__(256, 3) void crit_main(
    const int*   __restrict__ sta_loc,
    const int*   __restrict__ nei_loc,
    const int*   __restrict__ rand_numbers,
    const float* __restrict__ sta_emb,
    const float* __restrict__ nei_emb,
    const float* __restrict__ mask,
    const float* __restrict__ rand_vals,
    const float* __restrict__ t_rand,
    float*       __restrict__ out)
{
    __shared__ __align__(16) unsigned s_neiT[TP_][68];  // (sign<<31)|abs, transposed
    __shared__ __align__(16) float    s_PQ[TP_][68];    // w*B/64
    __shared__ __align__(16) float    s_P2[TP_][68];    // w*B^2
    __shared__ __align__(16) float    s_sw2[68];        // w/16384
    __shared__ __align__(16) float    s_t32[64];        // w*cm^2 per row
    __shared__ unsigned s_cnc[C_][TP_];
    __shared__ float    s_loss[C_][TP_];                // expanded loss minus SP2[p]
    __shared__ float    s_mask[S_];
    __shared__ float    s_rv[TP_], s_rl[TP_], s_red2[TP_];

    const int t    = blockIdx.x;
    const int tid  = threadIdx.x;
    const int lane = tid & 31;
    const int warp = tid >> 5;
    const int q    = lane & 7;             // == p for this thread

    // ---------------- inline int64 detection (per-warp, no barrier) ----------------
    int dlo = sta_loc[2 * lane];
    int dhi = sta_loc[2 * lane + 1];
    unsigned bmll = __ballot_sync(0xffffffffu, dhi == (dlo >> 31));
    const int str = (bmll == 0xffffffffu) ? 2 : 1;

    // ---------------- small loads (everything off the critical path, issued early) ----------------
    const int row0 = warp * 8 + (lane >> 3);   // 0..3 within warp's 8-row span
    const int row1 = row0 + 4;
    const int sl  = sta_loc[((size_t)t * TP_ + q) * str];
    int   nbr0 = nei_loc[(((size_t)t * S_ + row0) * TP_ + q) * str];
    int   nbr1 = nei_loc[(((size_t)t * S_ + row1) * TP_ + q) * str];
    float mr0  = mask[(size_t)t * S_ + row0];
    float mr1  = mask[(size_t)t * S_ + row1];
    int   rn   = rand_numbers[((size_t)t * 256 + tid) * str];
    if (tid < S_) s_mask[tid] = mask[(size_t)t * S_ + tid];
    float tr = 0.f;
    if (tid < TP_) {
        s_rv[tid] = rand_vals[(size_t)t * TP_ + tid];
        tr        = t_rand[t];
    }

    // ---------------- |sta|^2 within each 8-lane group ----------------
    const float4* sg4 = (const float4*)(sta_emb + (size_t)t * D_);
    float ns = 0.f;
    #pragma unroll
    for (int j = 0; j < 8; j++) {
        float4 a = sg4[q + 8 * j];
        ns = fmaf(a.x, a.x, ns); ns = fmaf(a.y, a.y, ns);
        ns = fmaf(a.z, a.z, ns); ns = fmaf(a.w, a.w, ns);
    }
    #pragma unroll
    for (int o = 1; o < 8; o <<= 1) ns += __shfl_xor_sync(0xffffffffu, ns, o);
    const float rns = rsqrtf(ns);

    // ---------------- B': preload BOTH rows, then dual independent FMA chains ----------------
    float dot0 = 0.f, nn0 = 0.f, dot1 = 0.f, nn1 = 0.f;
    {
        const float4* nr0 = (const float4*)(nei_emb + ((size_t)t * S_ + row0) * D_);
        const float4* nr1 = (const float4*)(nei_emb + ((size_t)t * S_ + row1) * D_);
        float4 b0[8], b1[8];
        #pragma unroll
        for (int j = 0; j < 8; j++) b0[j] = nr0[q + 8 * j];
        #pragma unroll
        for (int j = 0; j < 8; j++) b1[j] = nr1[q + 8 * j];
        #pragma unroll
        for (int j = 0; j < 8; j++) {
            float4 a = sg4[q + 8 * j];                 // L1 hit, shared by both rows
            dot0 = fmaf(a.x, b0[j].x, dot0); dot0 = fmaf(a.y, b0[j].y, dot0);
            dot0 = fmaf(a.z, b0[j].z, dot0); dot0 = fmaf(a.w, b0[j].w, dot0);
            nn0  = fmaf(b0[j].x, b0[j].x, nn0); nn0 = fmaf(b0[j].y, b0[j].y, nn0);
            nn0  = fmaf(b0[j].z, b0[j].z, nn0); nn0 = fmaf(b0[j].w, b0[j].w, nn0);
            dot1 = fmaf(a.x, b1[j].x, dot1); dot1 = fmaf(a.y, b1[j].y, dot1);
            dot1 = fmaf(a.z, b1[j].z, dot1); dot1 = fmaf(a.w, b1[j].w, dot1);
            nn1  = fmaf(b1[j].x, b1[j].x, nn1); nn1 = fmaf(b1[j].y, b1[j].y, nn1);
            nn1  = fmaf(b1[j].z, b1[j].z, nn1); nn1 = fmaf(b1[j].w, b1[j].w, nn1);
        }
    }

    // ---------------- per-row epilogue: cos_sn + reductions + C' coefficients ----------------
    #pragma unroll
    for (int it = 0; it < 2; it++) {
        int   row = it ? row1 : row0;
        float dot = it ? dot1 : dot0;
        float nn  = it ? nn1  : nn0;
        int   nb  = it ? nbr1 : nbr0;
        float mr  = it ? mr1  : mr0;

        int sg = ((nb ^ sl) < 0);
        int na = nb < 0 ? -nb : nb;
        int aa = sl < 0 ? -sl : sl;
        unsigned x = (unsigned)(na ^ aa) + 1u;
        int v  = __clz((int)x) - 16;
        int iv = sg ? -v : v;
        float cs = (float)iv * 0.0625f;
        s_neiT[q][row] = (unsigned)na | (nb < 0 ? 0x80000000u : 0u);
        float cssum = cs;
        #pragma unroll
        for (int o = 1; o < 8; o <<= 1) {
            dot   += __shfl_xor_sync(0xffffffffu, dot,   o);
            nn    += __shfl_xor_sync(0xffffffffu, nn,    o);
            cssum += __shfl_xor_sync(0xffffffffu, cssum, o);
        }
        float w = 0.f, cm = 0.f;
        if (q == 0) {
            float eu = dot * rsqrtf(nn) * rns;
            w  = fabsf(eu) * mr;                       // lth factored out
            cm = fmaf(cssum, 0.125f, -eu);             // cssum/8 - eu
        }
        w  = __shfl_sync(0xffffffffu, w,  0, 8);
        cm = __shfl_sync(0xffffffffu, cm, 0, 8);
        float B  = fmaf(cs, -0.125f, cm);
        float wB = w * B;
        s_PQ[q][row] = wB * 0.015625f;                 // w*B/64
        s_P2[q][row] = wB * B;                         // w*B^2
        if (q == 0) {
            s_sw2[row] = w * 6.103515625e-05f;         // w/16384
            s_t32[row] = w * cm * cm;
        }
    }

    // ---------------- E: cnc packed; F constants in registers ----------------
    unsigned ca0, ca1, sflip;
    {
        int k = tid >> 4, c = tid >> 3;                // c = 2k+j
        int r = sl ^ (1 << k) ^ (rn & ((1 << k) - 1));
        ca0 = pack_sgnabs(r);
        ca1 = pack_sgnabs(-r);
        sflip = (ca0 ^ ca1) & 0x80000000u;             // 0 iff r==0
        s_cnc[c][q]      = ca0;
        s_cnc[c + 33][q] = ca1;
        if (tid < TP_) s_cnc[32][tid] = pack_sgnabs(sl);
    }
    __syncthreads();                                   // barrier 1

    // ---------------- F: expanded loss, both mirrors from one chain ----------------
    {
        const int c0 = tid >> 3;                       // 0..31
        float accA = 0.f, accB = 0.f;
        const int4*   nt4 = (const int4*)&s_neiT[q][0];
        const float4* pqv = (const float4*)&s_PQ[q][0];
        const float4* swp = (const float4*)s_sw2;
        #pragma unroll
        for (int s4 = 0; s4 < 16; s4++) {
            int4   nv = nt4[s4];
            float4 Pq = pqv[s4];
            float4 sw = swp[s4];
            #pragma unroll
            for (int i = 0; i < 4; i++) {
                unsigned ne = (i == 0) ? (unsigned)nv.x : (i == 1) ? (unsigned)nv.y
                            : (i == 2) ? (unsigned)nv.z : (unsigned)nv.w;
                float PQ  = (i == 0) ? Pq.x : (i == 1) ? Pq.y : (i == 2) ? Pq.z : Pq.w;
                float sw2 = (i == 0) ? sw.x : (i == 1) ? sw.y : (i == 2) ? sw.z : sw.w;
                unsigned xr = ca0 ^ ne;
                unsigned x1 = (xr & 0x1FFFFu) + 1u;
                float uf = (float)(__clz((int)x1) - 16);
                float us = __int_as_float(__float_as_int(uf) ^ (xr & 0x80000000u));
                accA = fmaf(uf * uf, sw2, accA);
                accB = fmaf(us, PQ, accB);
            }
        }
        float accBs = __int_as_float(__float_as_int(accB) ^ sflip);
        s_loss[c0][q]      = accA + accB;              // true loss - SP2[p]
        s_loss[c0 + 33][q] = accA + accBs;
    }
    __syncthreads();                                   // barrier 2

    // ---------------- G: argmin, selection, outputs ----------------
    if (tid < TP_) {
        float SP2 = 0.f;
        const float4* pp = (const float4*)&s_P2[tid][0];
        #pragma unroll
        for (int j = 0; j < 16; j++) {
            float4 v4 = pp[j];
            SP2 += v4.x + v4.y + v4.z + v4.w;
        }
        float t32s = 0.f;
        const float4* tt = (const float4*)s_t32;
        #pragma unroll
        for (int j = 0; j < 16; j++) {
            float4 v4 = tt[j];
            t32s += v4.x + v4.y + v4.z + v4.w;
        }
        float l32adj = t32s - SP2;

        float best = s_loss[0][tid]; int bc = 0;
        #pragma unroll
        for (int c = 1; c < C_; c++) {
            float v = (c == 32) ? l32adj : s_loss[c][tid];
            if (v < best) { best = v; bc = c; }        // first-occurrence argmin
        }
        float rv = s_rv[tid]; int rank = 0;
        #pragma unroll
        for (int qq = 0; qq < 8; qq++) {
            float o = s_rv[qq];
            rank += (o < rv) || (o == rv && qq < tid); // stable argsort rank
        }
        int selg = (tr < 0.8f);
        int ci = (rank < 4) ? (selg ? bc : 32) : 32;
        unsigned pk = s_cnc[ci][tid];
        int val = (pk & 0x80000000u) ? -(int)(pk & 0x7fffffffu) : (int)pk;
        out[(size_t)t * TP_ + tid] = (float)val;
        s_rl[tid] = (ci == 32) ? t32s : (s_loss[ci][tid] + SP2);
        float m8 = 0.f;
        #pragma unroll
        for (int j = 0; j < 8; j++) m8 += s_mask[tid * 8 + j];
        s_red2[tid] = m8;
        __syncwarp(0x000000ffu);
        if (tid == 0) {
            float rl = 0.f, lth = 0.f;
            #pragma unroll
            for (int qq = 0; qq < 8; qq++) { rl += s_rl[qq]; lth += s_red2[qq]; }
            out[(size_t)T_ * TP_ + t] = rl * 0.125f / (lth + 1e-12f);
        }
    }
}

extern "C" void kernel_launch(void* const* d_in, const int* in_sizes, int n_in,
                              void* d_out, int out_size) {
    (void)in_sizes; (void)n_in; (void)out_size;
    const int*   sta_loc      = (const int*)  d_in[0];
    const int*   nei_loc      = (const int*)  d_in[1];
    const int*   rand_numbers = (const int*)  d_in[2];
    const float* sta_emb      = (const float*)d_in[3];
    const float* nei_emb      = (const float*)d_in[4];
    const float* mask         = (const float*)d_in[5];
    const float* rand_vals    = (const float*)d_in[6];
    const float* t_rand       = (const float*)d_in[7];
    float* out = (float*)d_out;

    crit_main<<<T_, 256>>>(sta_loc, nei_loc, rand_numbers,
                           sta_emb, nei_emb, mask, rand_vals, t_rand, out);
}